// round 10
// baseline (speedup 1.0000x reference)
#include <cuda_runtime.h>
#include <cuda_bf16.h>
#include <math.h>

#define N_NODES   100000
#define N_EDGES   6400000
#define F_IN      128
#define F_HID     16
#define N_CLASSES 10
#define SCAN_B    1024
#define SCAN_G    ((N_NODES + SCAN_B - 1) / SCAN_B)   // 98

// ---- scratch (device globals; referenced ONLY from device code) ----
__device__ int   g_deg [N_NODES];
__device__ int   g_off [N_NODES];
__device__ int   g_cur [N_NODES];
__device__ int   g_bsum[SCAN_G];
__device__ float g_dinv[N_NODES];
__device__ int   g_csrc[N_EDGES];                           // src ids grouped by dst
__device__ __align__(32) __nv_bfloat16 g_h1b[N_NODES * 16]; // (x@W1)*dinv
__device__ __align__(32) __nv_bfloat16 g_h2b[N_NODES * 16]; // (z@W2)*dinv (10+pad)
__device__ __align__(16) float g_z[N_NODES * F_HID];        // relu(dinv*agg1 + b1)

__device__ const float* g_xp;
__device__ const int*   g_eip;

// ---------------------------------------------------------------- probe + zero deg
__global__ void probe_zero_kernel(const void* a, const void* b) {
    int i = blockIdx.x * blockDim.x + threadIdx.x;
    if (i == 0) {
        const unsigned* ua = (const unsigned*)a;
        bool a_is_int = true;
        for (int k = 0; k < 16; k++)
            if (ua[k] >= 100000u) { a_is_int = false; break; }
        if (a_is_int) { g_eip = (const int*)a; g_xp = (const float*)b; }
        else          { g_eip = (const int*)b; g_xp = (const float*)a; }
    }
    if (i < N_NODES) g_deg[i] = 0;
}

// ---------------------------------------------------------------- degree (int2 over dst)
__global__ void degree_kernel() {
    int t = blockIdx.x * blockDim.x + threadIdx.x;
    if (t >= N_EDGES / 2) return;
    int2 d = ((const int2*)(g_eip + N_EDGES))[t];
    atomicAdd(&g_deg[d.x], 1);
    atomicAdd(&g_deg[d.y], 1);
}

// ---------------------------------------------------------------- scan A (+ dinv fused)
__global__ void scanA_kernel() {
    __shared__ int swarp[32];
    int i = blockIdx.x * SCAN_B + threadIdx.x;
    int lane = threadIdx.x & 31, wid = threadIdx.x >> 5;
    int v = (i < N_NODES) ? g_deg[i] : 0;
    if (i < N_NODES) g_dinv[i] = rsqrtf((float)(v + 1));
    int x = v;
    #pragma unroll
    for (int o = 1; o < 32; o <<= 1) {
        int t = __shfl_up_sync(0xffffffffu, x, o);
        if (lane >= o) x += t;
    }
    if (lane == 31) swarp[wid] = x;
    __syncthreads();
    if (wid == 0) {
        int y = swarp[lane];
        #pragma unroll
        for (int o = 1; o < 32; o <<= 1) {
            int t = __shfl_up_sync(0xffffffffu, y, o);
            if (lane >= o) y += t;
        }
        swarp[lane] = y;
    }
    __syncthreads();
    int excl = x - v + (wid > 0 ? swarp[wid - 1] : 0);
    if (i < N_NODES) g_off[i] = excl;
    if (threadIdx.x == SCAN_B - 1) g_bsum[blockIdx.x] = excl + v;
}

// ---------------------------------------------------------------- scan B
__global__ void scanB_kernel() {
    __shared__ int s[128];
    int t = threadIdx.x;
    s[t] = (t < SCAN_G) ? g_bsum[t] : 0;
    __syncthreads();
    for (int o = 1; o < 128; o <<= 1) {
        int v = (t >= o) ? s[t - o] : 0;
        __syncthreads();
        s[t] += v;
        __syncthreads();
    }
    if (t < SCAN_G) g_bsum[t] = (t > 0) ? s[t - 1] : 0;
}

// ---------------------------------------------------------------- scan C
__global__ void scanC_kernel() {
    int i = blockIdx.x * SCAN_B + threadIdx.x;
    if (i < N_NODES) {
        int o = g_off[i] + g_bsum[blockIdx.x];
        g_off[i] = o;
        g_cur[i] = o;
    }
}

// ---------------------------------------------------------------- placement (int2 edges)
__global__ void place_kernel() {
    int t = blockIdx.x * blockDim.x + threadIdx.x;
    if (t >= N_EDGES / 2) return;
    int2 s = ((const int2*)g_eip)[t];
    int2 d = ((const int2*)(g_eip + N_EDGES))[t];
    int p0 = atomicAdd(&g_cur[d.x], 1);
    g_csrc[p0] = s.x;
    int p1 = atomicAdd(&g_cur[d.y], 1);
    g_csrc[p1] = s.y;
}

// ---------------------------------------------------------------- h1b = bf16((x @ W1) * dinv)
__global__ void gemm1_kernel(const float* __restrict__ W1) {
    __shared__ float sW[F_IN * F_HID];
    int tid = threadIdx.x;
    #pragma unroll
    for (int j = 0; j < 16; j++) sW[tid * 16 + j] = W1[tid * 16 + j];
    __syncthreads();

    int row = blockIdx.x * 128 + tid;
    if (row >= N_NODES) return;

    const float4* xr = (const float4*)(g_xp + (size_t)row * F_IN);
    float acc[F_HID];
    #pragma unroll
    for (int f = 0; f < F_HID; f++) acc[f] = 0.f;

    #pragma unroll 4
    for (int k4 = 0; k4 < F_IN / 4; k4++) {
        float4 xv = xr[k4];
        const float* wk = &sW[k4 * 4 * F_HID];
        #pragma unroll
        for (int f = 0; f < F_HID; f++)
            acc[f] += xv.x * wk[f] + xv.y * wk[F_HID + f]
                    + xv.z * wk[2 * F_HID + f] + xv.w * wk[3 * F_HID + f];
    }

    float di = g_dinv[row];
    unsigned w[8];
    #pragma unroll
    for (int k = 0; k < 8; k++) {
        __nv_bfloat162 p = __floats2bfloat162_rn(acc[2 * k] * di, acc[2 * k + 1] * di);
        w[k] = *(unsigned*)&p;
    }
    uint4* o = (uint4*)(g_h1b + (size_t)row * 16);
    o[0] = make_uint4(w[0], w[1], w[2], w[3]);
    o[1] = make_uint4(w[4], w[5], w[6], w[7]);
}

// ---- gather helper: accumulate one bf16 row quad ----
__device__ __forceinline__ void acc_row(const __nv_bfloat16* hb, int s, int q,
                                        float& a0, float& a1, float& a2, float& a3) {
    uint2 r = *(const uint2*)(hb + (size_t)s * 16 + q * 4);
    float2 x0 = __bfloat1622float2(*(__nv_bfloat162*)&r.x);
    float2 x1 = __bfloat1622float2(*(__nv_bfloat162*)&r.y);
    a0 += x0.x; a1 += x0.y; a2 += x1.x; a3 += x1.y;
}

// ---------------------------------------------------------------- aggregate (warp/node, bf16 gather, fp32 accum)
// One warp per node, one block per 8 nodes (max parallelism for latency hiding).
// lane: q = lane&3 (8B chunk), ei = lane>>2 (8 edge slots). x4 unrolled gather.
// LAYER 1: z = relu(dinv*A + b1) fp32.  LAYER 2: fused log_softmax -> out.
template<int LAYER>
__global__ void aggregate_kernel(const float* __restrict__ bias, float* __restrict__ out) {
    int node = blockIdx.x * 8 + (threadIdx.x >> 5);
    if (node >= N_NODES) return;
    int lane = threadIdx.x & 31;
    int q  = lane & 3;
    int ei = lane >> 2;

    const __nv_bfloat16* hb = (LAYER == 1) ? g_h1b : g_h2b;
    int beg = g_off[node];
    int deg = g_deg[node];

    float a0 = 0.f, a1 = 0.f, a2 = 0.f, a3 = 0.f;
    if (ei == 0) acc_row(hb, node, q, a0, a1, a2, a3);  // self-loop term

    int j = ei;
    for (; j + 24 < deg; j += 32) {
        int s0 = g_csrc[beg + j];
        int s1 = g_csrc[beg + j + 8];
        int s2 = g_csrc[beg + j + 16];
        int s3 = g_csrc[beg + j + 24];
        acc_row(hb, s0, q, a0, a1, a2, a3);
        acc_row(hb, s1, q, a0, a1, a2, a3);
        acc_row(hb, s2, q, a0, a1, a2, a3);
        acc_row(hb, s3, q, a0, a1, a2, a3);
    }
    for (; j < deg; j += 8) {
        int s0 = g_csrc[beg + j];
        acc_row(hb, s0, q, a0, a1, a2, a3);
    }

    // reduce across edge slots (lane bits 2..4); afterwards all lanes hold full sums
    #pragma unroll
    for (int m = 4; m <= 16; m <<= 1) {
        a0 += __shfl_xor_sync(0xffffffffu, a0, m);
        a1 += __shfl_xor_sync(0xffffffffu, a1, m);
        a2 += __shfl_xor_sync(0xffffffffu, a2, m);
        a3 += __shfl_xor_sync(0xffffffffu, a3, m);
    }

    float di = g_dinv[node];

    if (LAYER == 1) {
        if (ei == 0) {
            float4 b = ((const float4*)bias)[q];
            float4 r;
            r.x = fmaxf(di * a0 + b.x, 0.f);
            r.y = fmaxf(di * a1 + b.y, 0.f);
            r.z = fmaxf(di * a2 + b.z, 0.f);
            r.w = fmaxf(di * a3 + b.w, 0.f);
            ((float4*)(g_z + (size_t)node * 16))[q] = r;
        }
    } else {
        // fused log_softmax (lane q holds classes 4q..4q+3)
        float l[4];
        l[0] = di * a0; l[1] = di * a1; l[2] = di * a2; l[3] = di * a3;
        int base = q * 4;
        float mx = -1e30f;
        #pragma unroll
        for (int k = 0; k < 4; k++) {
            if (base + k < N_CLASSES) { l[k] += bias[base + k]; mx = fmaxf(mx, l[k]); }
        }
        mx = fmaxf(mx, __shfl_xor_sync(0xffffffffu, mx, 1));
        mx = fmaxf(mx, __shfl_xor_sync(0xffffffffu, mx, 2));
        float se = 0.f;
        #pragma unroll
        for (int k = 0; k < 4; k++)
            if (base + k < N_CLASSES) se += expf(l[k] - mx);
        se += __shfl_xor_sync(0xffffffffu, se, 1);
        se += __shfl_xor_sync(0xffffffffu, se, 2);
        float ls = mx + logf(se);
        if (ei == 0) {
            float* op = out + (size_t)node * N_CLASSES + base;
            if (q < 2) {
                *(float2*)(op)     = make_float2(l[0] - ls, l[1] - ls);
                *(float2*)(op + 2) = make_float2(l[2] - ls, l[3] - ls);
            } else if (q == 2) {
                *(float2*)(op) = make_float2(l[0] - ls, l[1] - ls);
            }
        }
    }
}

// ---------------------------------------------------------------- mid: h2b = bf16((z @ W2) * dinv), padded
__global__ void mid_kernel(const float* __restrict__ W2) {
    __shared__ float sW2[F_HID * N_CLASSES];
    int tid = threadIdx.x;
    if (tid < F_HID * N_CLASSES) sW2[tid] = W2[tid];
    __syncthreads();

    int i = blockIdx.x * blockDim.x + tid;
    if (i >= N_NODES) return;

    float z[F_HID];
    const float4* zp = (const float4*)(g_z + (size_t)i * F_HID);
    #pragma unroll
    for (int k = 0; k < 4; k++) {
        float4 v = zp[k];
        z[k * 4 + 0] = v.x; z[k * 4 + 1] = v.y; z[k * 4 + 2] = v.z; z[k * 4 + 3] = v.w;
    }

    float di = g_dinv[i];
    float o[F_HID];
    #pragma unroll
    for (int c = 0; c < N_CLASSES; c++) {
        float s = 0.f;
        #pragma unroll
        for (int f = 0; f < F_HID; f++) s += z[f] * sW2[f * N_CLASSES + c];
        o[c] = s * di;
    }
    #pragma unroll
    for (int c = N_CLASSES; c < F_HID; c++) o[c] = 0.f;

    unsigned w[8];
    #pragma unroll
    for (int k = 0; k < 8; k++) {
        __nv_bfloat162 p = __floats2bfloat162_rn(o[2 * k], o[2 * k + 1]);
        w[k] = *(unsigned*)&p;
    }
    uint4* op = (uint4*)(g_h2b + (size_t)i * 16);
    op[0] = make_uint4(w[0], w[1], w[2], w[3]);
    op[1] = make_uint4(w[4], w[5], w[6], w[7]);
}

// ---------------------------------------------------------------- launch
extern "C" void kernel_launch(void* const* d_in, const int* in_sizes, int n_in,
                              void* d_out, int out_size) {
    const float *W1 = 0, *b1 = 0, *W2 = 0, *b2 = 0;
    const void *big_a = 0, *big_b = 0;
    for (int i = 0; i < n_in; i++) {
        switch (in_sizes[i]) {
            case F_IN * F_HID:      W1 = (const float*)d_in[i]; break;
            case F_HID:             b1 = (const float*)d_in[i]; break;
            case F_HID * N_CLASSES: W2 = (const float*)d_in[i]; break;
            case N_CLASSES:         b2 = (const float*)d_in[i]; break;
            default:
                if (!big_a) big_a = d_in[i]; else big_b = d_in[i];
        }
    }
    float* out = (float*)d_out;

    const int T = 256;
    const int NODE_G  = (N_NODES + T - 1) / T;
    const int EDGE2_G = (N_EDGES / 2 + T - 1) / T;
    const int AGG_G   = (N_NODES + 7) / 8;   // warp per node, 8 warps/block

    probe_zero_kernel<<<NODE_G, T>>>(big_a, big_b);
    degree_kernel<<<EDGE2_G, T>>>();
    scanA_kernel<<<SCAN_G, SCAN_B>>>();
    scanB_kernel<<<1, 128>>>();
    scanC_kernel<<<SCAN_G, SCAN_B>>>();
    place_kernel<<<EDGE2_G, T>>>();
    gemm1_kernel<<<(N_NODES + 127) / 128, 128>>>(W1);

    aggregate_kernel<1><<<AGG_G, T>>>(b1, nullptr);
    mid_kernel<<<NODE_G, T>>>(W2);
    aggregate_kernel<2><<<AGG_G, T>>>(b2, out);
}

// round 13
// speedup vs baseline: 1.3227x; 1.3227x over previous
#include <cuda_runtime.h>
#include <cuda_bf16.h>
#include <math.h>

#define N_NODES   100000
#define N_EDGES   6400000
#define F_IN      128
#define F_HID     16
#define N_CLASSES 10
#define SCAN_B    1024
#define SCAN_G    ((N_NODES + SCAN_B - 1) / SCAN_B)   // 98

// ---- scratch (device globals; referenced ONLY from device code) ----
__device__ int   g_deg [N_NODES];
__device__ int   g_off [N_NODES];
__device__ int   g_cur [N_NODES];
__device__ int   g_bsum[SCAN_G];
__device__ float g_dinv[N_NODES];
__device__ int   g_csrc[N_EDGES];                           // src ids grouped by dst
__device__ __align__(32) __nv_bfloat16 g_h1b[N_NODES * 16]; // (x@W1)*dinv
__device__ __align__(32) __nv_bfloat16 g_h2b[N_NODES * 16]; // (z@W2)*dinv (10+pad)
__device__ __align__(16) float g_z[N_NODES * F_HID];        // relu(dinv*agg1 + b1)

__device__ const float* g_xp;
__device__ const int*   g_eip;

// ---------------------------------------------------------------- probe + zero deg
__global__ void probe_zero_kernel(const void* a, const void* b) {
    int i = blockIdx.x * blockDim.x + threadIdx.x;
    if (i == 0) {
        const unsigned* ua = (const unsigned*)a;
        bool a_is_int = true;
        for (int k = 0; k < 16; k++)
            if (ua[k] >= 100000u) { a_is_int = false; break; }
        if (a_is_int) { g_eip = (const int*)a; g_xp = (const float*)b; }
        else          { g_eip = (const int*)b; g_xp = (const float*)a; }
    }
    if (i < N_NODES) g_deg[i] = 0;
}

// ---------------------------------------------------------------- degree (1 thread/edge: max MLP)
__global__ void degree_kernel() {
    int e = blockIdx.x * blockDim.x + threadIdx.x;
    const int* dst = g_eip + N_EDGES;
    if (e < N_EDGES) atomicAdd(&g_deg[dst[e]], 1);
}

// ---------------------------------------------------------------- scan A (+ dinv fused)
__global__ void scanA_kernel() {
    __shared__ int swarp[32];
    int i = blockIdx.x * SCAN_B + threadIdx.x;
    int lane = threadIdx.x & 31, wid = threadIdx.x >> 5;
    int v = (i < N_NODES) ? g_deg[i] : 0;
    if (i < N_NODES) g_dinv[i] = rsqrtf((float)(v + 1));
    int x = v;
    #pragma unroll
    for (int o = 1; o < 32; o <<= 1) {
        int t = __shfl_up_sync(0xffffffffu, x, o);
        if (lane >= o) x += t;
    }
    if (lane == 31) swarp[wid] = x;
    __syncthreads();
    if (wid == 0) {
        int y = swarp[lane];
        #pragma unroll
        for (int o = 1; o < 32; o <<= 1) {
            int t = __shfl_up_sync(0xffffffffu, y, o);
            if (lane >= o) y += t;
        }
        swarp[lane] = y;
    }
    __syncthreads();
    int excl = x - v + (wid > 0 ? swarp[wid - 1] : 0);
    if (i < N_NODES) g_off[i] = excl;
    if (threadIdx.x == SCAN_B - 1) g_bsum[blockIdx.x] = excl + v;
}

// ---------------------------------------------------------------- scan C (scanB folded in)
// Warp 0 of each block reduces g_bsum[0..blockIdx.x-1]; broadcast via shared.
__global__ void scanC_kernel() {
    __shared__ int sbase;
    if (threadIdx.x < 32) {
        int lane = threadIdx.x;
        int acc = 0;
        #pragma unroll
        for (int k = 0; k < (SCAN_G + 31) / 32; k++) {
            int idx = k * 32 + lane;
            if (idx < blockIdx.x) acc += g_bsum[idx];
        }
        #pragma unroll
        for (int m = 16; m >= 1; m >>= 1)
            acc += __shfl_xor_sync(0xffffffffu, acc, m);
        if (lane == 0) sbase = acc;
    }
    __syncthreads();
    int i = blockIdx.x * SCAN_B + threadIdx.x;
    if (i < N_NODES) {
        int o = g_off[i] + sbase;
        g_off[i] = o;
        g_cur[i] = o;
    }
}

// ---------------------------------------------------------------- placement (1 thread/edge)
__global__ void place_kernel() {
    int e = blockIdx.x * blockDim.x + threadIdx.x;
    if (e >= N_EDGES) return;
    const int* src = g_eip;
    const int* dst = g_eip + N_EDGES;
    int d = dst[e];
    int p = atomicAdd(&g_cur[d], 1);
    g_csrc[p] = src[e];
}

// ---------------------------------------------------------------- h1b = bf16((x @ W1) * dinv)
__global__ void gemm1_kernel(const float* __restrict__ W1) {
    __shared__ float sW[F_IN * F_HID];
    int tid = threadIdx.x;
    #pragma unroll
    for (int j = 0; j < 16; j++) sW[tid * 16 + j] = W1[tid * 16 + j];
    __syncthreads();

    int row = blockIdx.x * 128 + tid;
    if (row >= N_NODES) return;

    const float4* xr = (const float4*)(g_xp + (size_t)row * F_IN);
    float acc[F_HID];
    #pragma unroll
    for (int f = 0; f < F_HID; f++) acc[f] = 0.f;

    #pragma unroll 4
    for (int k4 = 0; k4 < F_IN / 4; k4++) {
        float4 xv = xr[k4];
        const float* wk = &sW[k4 * 4 * F_HID];
        #pragma unroll
        for (int f = 0; f < F_HID; f++)
            acc[f] += xv.x * wk[f] + xv.y * wk[F_HID + f]
                    + xv.z * wk[2 * F_HID + f] + xv.w * wk[3 * F_HID + f];
    }

    float di = g_dinv[row];
    unsigned w[8];
    #pragma unroll
    for (int k = 0; k < 8; k++) {
        __nv_bfloat162 p = __floats2bfloat162_rn(acc[2 * k] * di, acc[2 * k + 1] * di);
        w[k] = *(unsigned*)&p;
    }
    uint4* o = (uint4*)(g_h1b + (size_t)row * 16);
    o[0] = make_uint4(w[0], w[1], w[2], w[3]);
    o[1] = make_uint4(w[4], w[5], w[6], w[7]);
}

// ---- gather helper: accumulate one bf16 row quad ----
__device__ __forceinline__ void acc_row(const __nv_bfloat16* hb, int s, int q,
                                        float& a0, float& a1, float& a2, float& a3) {
    uint2 r = *(const uint2*)(hb + (size_t)s * 16 + q * 4);
    float2 x0 = __bfloat1622float2(*(__nv_bfloat162*)&r.x);
    float2 x1 = __bfloat1622float2(*(__nv_bfloat162*)&r.y);
    a0 += x0.x; a1 += x0.y; a2 += x1.x; a3 += x1.y;
}

// ---------------------------------------------------------------- aggregate (warp/node, R7 loop shape)
template<int LAYER>
__global__ void aggregate_kernel(const float* __restrict__ bias, float* __restrict__ out) {
    int node = blockIdx.x * 8 + (threadIdx.x >> 5);
    if (node >= N_NODES) return;
    int lane = threadIdx.x & 31;
    int q  = lane & 3;
    int ei = lane >> 2;

    const __nv_bfloat16* hb = (LAYER == 1) ? g_h1b : g_h2b;
    int beg = g_off[node];
    int deg = g_deg[node];

    float a0 = 0.f, a1 = 0.f, a2 = 0.f, a3 = 0.f;
    if (ei == 0) acc_row(hb, node, q, a0, a1, a2, a3);  // self-loop term

    int j = ei;
    for (; j + 8 < deg; j += 16) {
        int s0 = g_csrc[beg + j];
        int s1 = g_csrc[beg + j + 8];
        acc_row(hb, s0, q, a0, a1, a2, a3);
        acc_row(hb, s1, q, a0, a1, a2, a3);
    }
    if (j < deg) {
        int s0 = g_csrc[beg + j];
        acc_row(hb, s0, q, a0, a1, a2, a3);
    }

    #pragma unroll
    for (int m = 4; m <= 16; m <<= 1) {
        a0 += __shfl_xor_sync(0xffffffffu, a0, m);
        a1 += __shfl_xor_sync(0xffffffffu, a1, m);
        a2 += __shfl_xor_sync(0xffffffffu, a2, m);
        a3 += __shfl_xor_sync(0xffffffffu, a3, m);
    }

    float di = g_dinv[node];

    if (LAYER == 1) {
        if (ei == 0) {
            float4 b = ((const float4*)bias)[q];
            float4 r;
            r.x = fmaxf(di * a0 + b.x, 0.f);
            r.y = fmaxf(di * a1 + b.y, 0.f);
            r.z = fmaxf(di * a2 + b.z, 0.f);
            r.w = fmaxf(di * a3 + b.w, 0.f);
            ((float4*)(g_z + (size_t)node * 16))[q] = r;
        }
    } else {
        float l[4];
        l[0] = di * a0; l[1] = di * a1; l[2] = di * a2; l[3] = di * a3;
        int base = q * 4;
        float mx = -1e30f;
        #pragma unroll
        for (int k = 0; k < 4; k++) {
            if (base + k < N_CLASSES) { l[k] += bias[base + k]; mx = fmaxf(mx, l[k]); }
        }
        mx = fmaxf(mx, __shfl_xor_sync(0xffffffffu, mx, 1));
        mx = fmaxf(mx, __shfl_xor_sync(0xffffffffu, mx, 2));
        float se = 0.f;
        #pragma unroll
        for (int k = 0; k < 4; k++)
            if (base + k < N_CLASSES) se += expf(l[k] - mx);
        se += __shfl_xor_sync(0xffffffffu, se, 1);
        se += __shfl_xor_sync(0xffffffffu, se, 2);
        float ls = mx + logf(se);
        if (ei == 0) {
            float* op = out + (size_t)node * N_CLASSES + base;
            if (q < 2) {
                *(float2*)(op)     = make_float2(l[0] - ls, l[1] - ls);
                *(float2*)(op + 2) = make_float2(l[2] - ls, l[3] - ls);
            } else if (q == 2) {
                *(float2*)(op) = make_float2(l[0] - ls, l[1] - ls);
            }
        }
    }
}

// ---------------------------------------------------------------- mid: h2b = bf16((z @ W2) * dinv), padded
__global__ void mid_kernel(const float* __restrict__ W2) {
    __shared__ float sW2[F_HID * N_CLASSES];
    int tid = threadIdx.x;
    if (tid < F_HID * N_CLASSES) sW2[tid] = W2[tid];
    __syncthreads();

    int i = blockIdx.x * blockDim.x + tid;
    if (i >= N_NODES) return;

    float z[F_HID];
    const float4* zp = (const float4*)(g_z + (size_t)i * F_HID);
    #pragma unroll
    for (int k = 0; k < 4; k++) {
        float4 v = zp[k];
        z[k * 4 + 0] = v.x; z[k * 4 + 1] = v.y; z[k * 4 + 2] = v.z; z[k * 4 + 3] = v.w;
    }

    float di = g_dinv[i];
    float o[F_HID];
    #pragma unroll
    for (int c = 0; c < N_CLASSES; c++) {
        float s = 0.f;
        #pragma unroll
        for (int f = 0; f < F_HID; f++) s += z[f] * sW2[f * N_CLASSES + c];
        o[c] = s * di;
    }
    #pragma unroll
    for (int c = N_CLASSES; c < F_HID; c++) o[c] = 0.f;

    unsigned w[8];
    #pragma unroll
    for (int k = 0; k < 8; k++) {
        __nv_bfloat162 p = __floats2bfloat162_rn(o[2 * k], o[2 * k + 1]);
        w[k] = *(unsigned*)&p;
    }
    uint4* op = (uint4*)(g_h2b + (size_t)i * 16);
    op[0] = make_uint4(w[0], w[1], w[2], w[3]);
    op[1] = make_uint4(w[4], w[5], w[6], w[7]);
}

// ---------------------------------------------------------------- launch
extern "C" void kernel_launch(void* const* d_in, const int* in_sizes, int n_in,
                              void* d_out, int out_size) {
    const float *W1 = 0, *b1 = 0, *W2 = 0, *b2 = 0;
    const void *big_a = 0, *big_b = 0;
    for (int i = 0; i < n_in; i++) {
        switch (in_sizes[i]) {
            case F_IN * F_HID:      W1 = (const float*)d_in[i]; break;
            case F_HID:             b1 = (const float*)d_in[i]; break;
            case F_HID * N_CLASSES: W2 = (const float*)d_in[i]; break;
            case N_CLASSES:         b2 = (const float*)d_in[i]; break;
            default:
                if (!big_a) big_a = d_in[i]; else big_b = d_in[i];
        }
    }
    float* out = (float*)d_out;

    const int T = 256;
    const int NODE_G = (N_NODES + T - 1) / T;
    const int EDGE_G = (N_EDGES + T - 1) / T;
    const int AGG_G  = (N_NODES + 7) / 8;   // warp per node, 8 warps/block

    probe_zero_kernel<<<NODE_G, T>>>(big_a, big_b);
    degree_kernel<<<EDGE_G, T>>>();
    scanA_kernel<<<SCAN_G, SCAN_B>>>();
    scanC_kernel<<<SCAN_G, SCAN_B>>>();
    place_kernel<<<EDGE_G, T>>>();
    gemm1_kernel<<<(N_NODES + 127) / 128, 128>>>(W1);

    aggregate_kernel<1><<<AGG_G, T>>>(b1, nullptr);
    mid_kernel<<<NODE_G, T>>>(W2);
    aggregate_kernel<2><<<AGG_G, T>>>(b2, out);
}